// round 11
// baseline (speedup 1.0000x reference)
#include <cuda_runtime.h>
#include <cuda_bf16.h>
#include <math.h>
#include <stdint.h>

#define B_    8
#define N_    1024
#define M_    4096
#define C_    512
#define KNN   16
#define NCAND 32
#define ITERS 3

typedef __nv_bfloat16 bf16;

// ---------------- scratch (static device globals) ----------------
__device__ float g_nr   [(size_t)B_*M_*C_];
__device__ float g_nt   [(size_t)B_*N_*C_];
__device__ float g_corr [(size_t)N_*M_];      // single-batch slab (16 MB, L2-resident)
__device__ float g_q    [(size_t)B_*N_*C_];
__device__ float g_ctx  [(size_t)B_*N_*C_];
__device__ float g_slots[(size_t)B_*N_*C_];
__device__ float g_G    [(size_t)C_*C_];      // Wq @ Wk^T
__device__ float g_Wvo  [(size_t)C_*C_];      // Wv @ Wo
__device__ bf16  g_nr_bf[(size_t)B_*M_*C_];
__device__ bf16  g_nt_bf[(size_t)B_*N_*C_];
__device__ int   g_cand [(size_t)B_*N_*NCAND];
__device__ int   g_idx  [(size_t)B_*N_*KNN];

// ---------------- MMA helpers (validated) ----------------
__device__ __forceinline__ uint32_t sptr(const void* p) {
    uint32_t r;
    asm("{ .reg .u64 t; cvta.to.shared.u64 t, %1; cvt.u32.u64 %0, t; }" : "=r"(r) : "l"(p));
    return r;
}
__device__ __forceinline__ void ldm_x4(uint32_t& r0, uint32_t& r1, uint32_t& r2, uint32_t& r3, uint32_t a) {
    asm volatile("ldmatrix.sync.aligned.m8n8.x4.shared.b16 {%0,%1,%2,%3}, [%4];"
                 : "=r"(r0), "=r"(r1), "=r"(r2), "=r"(r3) : "r"(a));
}
__device__ __forceinline__ void mma_bf16(float* c, const uint32_t* a, const uint32_t* b) {
    asm volatile("mma.sync.aligned.m16n8k16.row.col.f32.bf16.bf16.f32 "
                 "{%0,%1,%2,%3}, {%4,%5,%6,%7}, {%8,%9}, {%0,%1,%2,%3};"
                 : "+f"(c[0]), "+f"(c[1]), "+f"(c[2]), "+f"(c[3])
                 : "r"(a[0]), "r"(a[1]), "r"(a[2]), "r"(a[3]), "r"(b[0]), "r"(b[1]));
}
__device__ __forceinline__ uint32_t swz(int row, int chunk) {
    return (uint32_t)(row * 64 + ((chunk ^ ((row >> 1) & 3)) << 4));
}

// ---------------- normalize rows + bf16 copy (validated) ----------------
__global__ void normalize_rows_bf(const float* __restrict__ x, float* __restrict__ y,
                                  bf16* __restrict__ ybf) {
    int row = blockIdx.x;
    const float4* xr = (const float4*)(x + (size_t)row * C_);
    float4 v = xr[threadIdx.x];
    float ss = v.x*v.x + v.y*v.y + v.z*v.z + v.w*v.w;
    #pragma unroll
    for (int o = 16; o; o >>= 1) ss += __shfl_down_sync(0xFFFFFFFFu, ss, o);
    __shared__ float red[4];
    if ((threadIdx.x & 31) == 0) red[threadIdx.x >> 5] = ss;
    __syncthreads();
    float tot = red[0] + red[1] + red[2] + red[3];
    float inv = 1.0f / sqrtf(tot);
    v.x *= inv; v.y *= inv; v.z *= inv; v.w *= inv;
    ((float4*)(y + (size_t)row * C_))[threadIdx.x] = v;
    __nv_bfloat162* o2 = (__nv_bfloat162*)(ybf + (size_t)row * C_);
    __nv_bfloat162 h0; h0.x = __float2bfloat16_rn(v.x); h0.y = __float2bfloat16_rn(v.y);
    __nv_bfloat162 h1; h1.x = __float2bfloat16_rn(v.z); h1.y = __float2bfloat16_rn(v.w);
    o2[threadIdx.x * 2] = h0; o2[threadIdx.x * 2 + 1] = h1;
}

// ---------------- corr GEMM (R8-verbatim synchronous bf16 MMA; single batch) ----------
__global__ __launch_bounds__(256) void gemm_corr(const bf16* __restrict__ A,
                                                 const bf16* __restrict__ Bm,
                                                 float* __restrict__ C) {
    A  += (size_t)blockIdx.z * N_ * C_;
    Bm += (size_t)blockIdx.z * M_ * C_;
    C  += (size_t)blockIdx.z * N_ * M_;
    __shared__ __align__(16) uint8_t sA[128 * 64];
    __shared__ __align__(16) uint8_t sB[128 * 64];
    uint32_t baseA = sptr(sA), baseB = sptr(sB);
    int tid = threadIdx.x, lane = tid & 31, w = tid >> 5;
    int wm = w & 1, wn = w >> 1;
    int row0 = blockIdx.y * 128, col0 = blockIdx.x * 128;
    float acc[4][4][4] = {};
    for (int kt = 0; kt < C_ / 32; ++kt) {
        int k0 = kt * 32;
        #pragma unroll
        for (int i = 0; i < 2; ++i) {
            int cid = tid + i * 256, r = cid >> 2, c = cid & 3;
            *(uint4*)(sA + swz(r, c)) = *(const uint4*)(A + (size_t)(row0 + r) * C_ + k0 + c * 8);
            *(uint4*)(sB + swz(r, c)) = *(const uint4*)(Bm + (size_t)(col0 + r) * C_ + k0 + c * 8);
        }
        __syncthreads();
        #pragma unroll
        for (int kk = 0; kk < 2; ++kk) {
            uint32_t b[4][2];
            #pragma unroll
            for (int jn = 0; jn < 2; ++jn) {
                int r = wn * 32 + jn * 16 + (lane & 7) + ((lane >> 4) << 3);
                int ck = kk * 2 + ((lane >> 3) & 1);
                ldm_x4(b[jn*2][0], b[jn*2][1], b[jn*2+1][0], b[jn*2+1][1], baseB + swz(r, ck));
            }
            #pragma unroll
            for (int im = 0; im < 4; ++im) {
                uint32_t a[4];
                int r = wm * 64 + im * 16 + (lane & 15);
                int ck = kk * 2 + (lane >> 4);
                ldm_x4(a[0], a[1], a[2], a[3], baseA + swz(r, ck));
                #pragma unroll
                for (int in = 0; in < 4; ++in) mma_bf16(acc[im][in], a, b[in]);
            }
        }
        __syncthreads();
    }
    int g = lane >> 2, t2 = (lane & 3) * 2;
    #pragma unroll
    for (int im = 0; im < 4; ++im)
        #pragma unroll
        for (int in = 0; in < 4; ++in) {
            int row = row0 + wm * 64 + im * 16 + g;
            int col = col0 + wn * 32 + in * 8 + t2;
            *(float2*)(C + (size_t)row * M_ + col)       = make_float2(acc[im][in][0], acc[im][in][1]);
            *(float2*)(C + (size_t)(row + 8) * M_ + col) = make_float2(acc[im][in][2], acc[im][in][3]);
        }
}

// ---------------- approx top-32 candidates (R8-verbatim scalar scan; single batch) -----
__global__ void cand32_kernel(const float* __restrict__ corr, int* __restrict__ out_idx) {
    int row  = blockIdx.x * (blockDim.x >> 5) + (threadIdx.x >> 5);
    int lane = threadIdx.x & 31;
    const float* cr = corr + (size_t)row * M_;
    float val[KNN];
    int   id [KNN];
    #pragma unroll
    for (int j = 0; j < KNN; ++j) { val[j] = -INFINITY; id[j] = 0x7FFFFFFF; }
    for (int m = lane; m < M_; m += 32) {
        float v = cr[m];
        if (v > val[KNN - 1]) {
            #pragma unroll
            for (int j = KNN - 1; j >= 0; --j) {
                bool shift = (j > 0) && (val[j - 1] < v);
                if (shift)            { val[j] = val[j - 1]; id[j] = id[j - 1]; }
                else if (val[j] < v)  { val[j] = v;          id[j] = m; }
            }
        }
    }
    int p = 0;
    for (int r = 0; r < NCAND; ++r) {
        float rv = (p < KNN) ? val[p] : -INFINITY;
        int   rm = (p < KNN) ? id[p]  : 0x7FFFFFFF;
        #pragma unroll
        for (int o = 16; o; o >>= 1) {
            float ov = __shfl_down_sync(0xFFFFFFFFu, rv, o);
            int   om = __shfl_down_sync(0xFFFFFFFFu, rm, o);
            if (ov > rv || (ov == rv && om < rm)) { rv = ov; rm = om; }
        }
        int wm = __shfl_sync(0xFFFFFFFFu, rm, 0);
        if (lane == 0) out_idx[(size_t)row * NCAND + r] = wm;
        if ((wm & 31) == lane) ++p;
    }
}

// ---------------- fp32 rescore (float4, sequential fmaf chain — validated) ----------
__global__ void rescore_kernel(const float* __restrict__ nt, const float* __restrict__ nr,
                               const int* __restrict__ cand, int* __restrict__ out_idx) {
    int warp = threadIdx.x >> 5, lane = threadIdx.x & 31;
    int row = blockIdx.x * 8 + warp;
    int b = row >> 10;
    int cm = cand[(size_t)row * NCAND + lane];
    const float* q  = nt + (size_t)row * C_;
    const float* kr = nr + ((size_t)b * M_ + cm) * C_;
    float acc = 0.f;
    #pragma unroll 8
    for (int k = 0; k < C_; k += 4) {
        float4 qa = *(const float4*)(q + k);
        float4 ka = *(const float4*)(kr + k);
        acc = fmaf(qa.x, ka.x, acc);
        acc = fmaf(qa.y, ka.y, acc);
        acc = fmaf(qa.z, ka.z, acc);
        acc = fmaf(qa.w, ka.w, acc);
    }
    bool taken = false;
    for (int r = 0; r < KNN; ++r) {
        float rv = taken ? -INFINITY : acc;
        int   rm = taken ? 0x7FFFFFFF : cm;
        #pragma unroll
        for (int o = 16; o; o >>= 1) {
            float ov = __shfl_down_sync(0xFFFFFFFFu, rv, o);
            int   om = __shfl_down_sync(0xFFFFFFFFu, rm, o);
            if (ov > rv || (ov == rv && om < rm)) { rv = ov; rm = om; }
        }
        int wm = __shfl_sync(0xFFFFFFFFu, rm, 0);
        if (lane == 0) out_idx[(size_t)row * KNN + r] = wm;
        if (wm == cm) taken = true;
    }
}

// ======================= fp32 OUTPUT PATH (R8 verbatim) =======================

__global__ __launch_bounds__(256) void sgemm_nn_128(const float* __restrict__ A,
                                                    const float* __restrict__ W,
                                                    const float* __restrict__ R,
                                                    float* __restrict__ C,
                                                    int M, int N, int K) {
    __shared__ float As[16][128];
    __shared__ float Bs[16][128];
    int tid = threadIdx.x;
    int tx = tid & 15, ty = tid >> 4;
    int row0 = blockIdx.y * 128, col0 = blockIdx.x * 128;
    float acc[8][8] = {};
    for (int k0 = 0; k0 < K; k0 += 16) {
        #pragma unroll
        for (int i = 0; i < 2; ++i) {
            int chunk = tid * 2 + i;
            int r = chunk >> 2, kq = (chunk & 3) << 2;
            float4 v = *(const float4*)(A + (size_t)(row0 + r) * K + k0 + kq);
            As[kq + 0][r] = v.x; As[kq + 1][r] = v.y;
            As[kq + 2][r] = v.z; As[kq + 3][r] = v.w;
        }
        #pragma unroll
        for (int i = 0; i < 2; ++i) {
            int chunk = tid * 2 + i;
            int kr = chunk >> 5, c4 = (chunk & 31) << 2;
            *(float4*)&Bs[kr][c4] = *(const float4*)(W + (size_t)(k0 + kr) * N + col0 + c4);
        }
        __syncthreads();
        #pragma unroll
        for (int kk = 0; kk < 16; ++kk) {
            float a[8], b[8];
            *(float4*)(a)     = *(float4*)&As[kk][ty * 8];
            *(float4*)(a + 4) = *(float4*)&As[kk][ty * 8 + 4];
            *(float4*)(b)     = *(float4*)&Bs[kk][tx * 8];
            *(float4*)(b + 4) = *(float4*)&Bs[kk][tx * 8 + 4];
            #pragma unroll
            for (int i = 0; i < 8; ++i)
                #pragma unroll
                for (int j = 0; j < 8; ++j)
                    acc[i][j] = fmaf(a[i], b[j], acc[i][j]);
        }
        __syncthreads();
    }
    #pragma unroll
    for (int i = 0; i < 8; ++i) {
        int row = row0 + ty * 8 + i;
        #pragma unroll
        for (int j4 = 0; j4 < 2; ++j4) {
            int col = col0 + tx * 8 + j4 * 4;
            float4 o;
            o.x = acc[i][j4*4+0]; o.y = acc[i][j4*4+1];
            o.z = acc[i][j4*4+2]; o.w = acc[i][j4*4+3];
            if (R) {
                float4 r = *(const float4*)(R + (size_t)row * N + col);
                o.x += r.x; o.y += r.y; o.z += r.z; o.w += r.w;
            }
            *(float4*)(C + (size_t)row * N + col) = o;
        }
    }
}

#define BM 64
#define BN 64
#define BK 16
__global__ void sgemm_nn(const float* __restrict__ A, const float* __restrict__ W,
                         const float* __restrict__ R, float* __restrict__ C,
                         int M, int N, int K) {
    __shared__ float As[BK][BM];
    __shared__ float Bs[BK][BN];
    int tid = threadIdx.x;
    int tx = tid & 15, ty = tid >> 4;
    int row0 = blockIdx.y * BM, col0 = blockIdx.x * BN;
    float acc[4][4] = {};
    for (int k0 = 0; k0 < K; k0 += BK) {
        {
            int r = tid >> 2, kq = (tid & 3) << 2;
            float4 v = *(const float4*)(A + (size_t)(row0 + r) * K + k0 + kq);
            As[kq + 0][r] = v.x; As[kq + 1][r] = v.y;
            As[kq + 2][r] = v.z; As[kq + 3][r] = v.w;
        }
        {
            int r = tid >> 4, c = (tid & 15) << 2;
            *(float4*)&Bs[r][c] = *(const float4*)(W + (size_t)(k0 + r) * N + col0 + c);
        }
        __syncthreads();
        #pragma unroll
        for (int kk = 0; kk < BK; ++kk) {
            float a[4], b[4];
            *(float4*)a = *(float4*)&As[kk][ty << 2];
            *(float4*)b = *(float4*)&Bs[kk][tx << 2];
            #pragma unroll
            for (int i = 0; i < 4; ++i)
                #pragma unroll
                for (int j = 0; j < 4; ++j)
                    acc[i][j] += a[i] * b[j];
        }
        __syncthreads();
    }
    #pragma unroll
    for (int i = 0; i < 4; ++i) {
        int row = row0 + (ty << 2) + i;
        float4 o;
        o.x = acc[i][0]; o.y = acc[i][1]; o.z = acc[i][2]; o.w = acc[i][3];
        if (R) {
            float4 r = *(const float4*)(R + (size_t)row * N + col0 + (tx << 2));
            o.x += r.x; o.y += r.y; o.z += r.z; o.w += r.w;
        }
        *(float4*)(C + (size_t)row * N + col0 + (tx << 2)) = o;
    }
}

__global__ void sgemm_nt_w(const float* __restrict__ A, const float* __restrict__ Bm,
                           float* __restrict__ C) {
    __shared__ float As[BK][BM];
    __shared__ float Bs[BK][BN];
    int tid = threadIdx.x;
    int tx = tid & 15, ty = tid >> 4;
    int row0 = blockIdx.y * BM, col0 = blockIdx.x * BN;
    float acc[4][4] = {};
    for (int k0 = 0; k0 < C_; k0 += BK) {
        int r = tid >> 2, kq = (tid & 3) << 2;
        {
            float4 v = *(const float4*)(A + (size_t)(row0 + r) * C_ + k0 + kq);
            As[kq + 0][r] = v.x; As[kq + 1][r] = v.y;
            As[kq + 2][r] = v.z; As[kq + 3][r] = v.w;
        }
        {
            float4 v = *(const float4*)(Bm + (size_t)(col0 + r) * C_ + k0 + kq);
            Bs[kq + 0][r] = v.x; Bs[kq + 1][r] = v.y;
            Bs[kq + 2][r] = v.z; Bs[kq + 3][r] = v.w;
        }
        __syncthreads();
        #pragma unroll
        for (int kk = 0; kk < BK; ++kk) {
            float a[4], b[4];
            *(float4*)a = *(float4*)&As[kk][ty << 2];
            *(float4*)b = *(float4*)&Bs[kk][tx << 2];
            #pragma unroll
            for (int i = 0; i < 4; ++i)
                #pragma unroll
                for (int j = 0; j < 4; ++j)
                    acc[i][j] += a[i] * b[j];
        }
        __syncthreads();
    }
    #pragma unroll
    for (int i = 0; i < 4; ++i) {
        int row = row0 + (ty << 2) + i;
        float4 o;
        o.x = acc[i][0]; o.y = acc[i][1]; o.z = acc[i][2]; o.w = acc[i][3];
        *(float4*)(C + (size_t)row * C_ + col0 + (tx << 2)) = o;
    }
}

// ---------------- attention (R8 verbatim) ----------------
__global__ void attn_kernel(const float* __restrict__ q, const float* __restrict__ ref,
                            const int* __restrict__ idx, float* __restrict__ ctx) {
    int row = blockIdx.x, b = row >> 10;
    int tid = threadIdx.x, warp = tid >> 5, lane = tid & 31;
    __shared__ float s_logits[KNN];
    __shared__ int   s_idx[KNN];
    if (tid < KNN) s_idx[tid] = idx[(size_t)row * KNN + tid];
    __syncthreads();
    const float* qrow = q + (size_t)row * C_;
    const float scale = 0.04419417382415922f;   // 1/sqrt(512)
    #pragma unroll
    for (int j = 0; j < 4; ++j) {
        int kk = warp * 4 + j;
        const float* krow = ref + ((size_t)b * M_ + s_idx[kk]) * C_;
        float acc = 0.f;
        #pragma unroll
        for (int c = lane * 4; c < C_; c += 128) {
            float4 qa = *(const float4*)(qrow + c);
            float4 ka = *(const float4*)(krow + c);
            acc += qa.x * ka.x + qa.y * ka.y + qa.z * ka.z + qa.w * ka.w;
        }
        #pragma unroll
        for (int o = 16; o; o >>= 1) acc += __shfl_down_sync(0xFFFFFFFFu, acc, o);
        if (lane == 0) s_logits[kk] = acc * scale;
    }
    __syncthreads();
    float mx = -INFINITY;
    #pragma unroll
    for (int k = 0; k < KNN; ++k) mx = fmaxf(mx, s_logits[k]);
    float wv[KNN]; float wsum = 0.f;
    #pragma unroll
    for (int k = 0; k < KNN; ++k) { wv[k] = expf(s_logits[k] - mx); wsum += wv[k]; }
    float inv = 1.0f / wsum;
    int c = tid * 4;
    float4 acc4 = {0.f, 0.f, 0.f, 0.f};
    #pragma unroll
    for (int k = 0; k < KNN; ++k) {
        const float4 va = *(const float4*)(ref + ((size_t)b * M_ + s_idx[k]) * C_ + c);
        float wk = wv[k] * inv;
        acc4.x += wk * va.x; acc4.y += wk * va.y;
        acc4.z += wk * va.z; acc4.w += wk * va.w;
    }
    *(float4*)(ctx + (size_t)row * C_ + c) = acc4;
}

// ---------------- launch ----------------
extern "C" void kernel_launch(void* const* d_in, const int* in_sizes, int n_in,
                              void* d_out, int out_size) {
    const float* slots_in = (const float*)d_in[0];
    const float* ref_list = (const float*)d_in[1];
    const float* Wq = (const float*)d_in[2];
    const float* Wk = (const float*)d_in[3];
    const float* Wv = (const float*)d_in[4];
    const float* Wo = (const float*)d_in[5];
    const float* ref = ref_list + ((size_t)in_sizes[1] - (size_t)B_ * M_ * C_);
    float* out = (float*)d_out;

    float *p_nr, *p_nt, *p_corr, *p_q, *p_ctx, *p_slots, *p_G, *p_Wvo;
    bf16 *p_nr_bf, *p_nt_bf;
    int *p_cand, *p_idx;
    cudaGetSymbolAddress((void**)&p_nr, g_nr);       cudaGetSymbolAddress((void**)&p_nt, g_nt);
    cudaGetSymbolAddress((void**)&p_corr, g_corr);   cudaGetSymbolAddress((void**)&p_q, g_q);
    cudaGetSymbolAddress((void**)&p_ctx, g_ctx);     cudaGetSymbolAddress((void**)&p_slots, g_slots);
    cudaGetSymbolAddress((void**)&p_G, g_G);         cudaGetSymbolAddress((void**)&p_Wvo, g_Wvo);
    cudaGetSymbolAddress((void**)&p_nr_bf, g_nr_bf); cudaGetSymbolAddress((void**)&p_nt_bf, g_nt_bf);
    cudaGetSymbolAddress((void**)&p_cand, g_cand);   cudaGetSymbolAddress((void**)&p_idx, g_idx);

    // ---- precompute ----
    normalize_rows_bf<<<B_ * M_, 128>>>(ref, p_nr, p_nr_bf);
    dim3 gW(C_ / BN, C_ / BM);
    sgemm_nt_w<<<gW, 256>>>(Wq, Wk, p_G);                        // G = Wq @ Wk^T
    sgemm_nn<<<gW, 256>>>(Wv, Wo, nullptr, p_Wvo, C_, C_, C_);   // Wvo = Wv @ Wo

    const float* cur = slots_in;
    for (int it = 0; it < ITERS; ++it) {
        float* dst = (it == ITERS - 1) ? out : p_slots;

        normalize_rows_bf<<<B_ * N_, 128>>>(cur, p_nt, p_nt_bf);

        // selection, batch-interleaved through a single L2-resident 16 MB corr slab
        dim3 gCorrB(M_ / 128, N_ / 128, 1);
        for (int b = 0; b < B_; ++b) {
            gemm_corr<<<gCorrB, 256>>>(p_nt_bf + (size_t)b * N_ * C_,
                                       p_nr_bf + (size_t)b * M_ * C_, p_corr);
            cand32_kernel<<<N_ / 8, 256>>>(p_corr, p_cand + (size_t)b * N_ * NCAND);
        }
        rescore_kernel<<<(B_ * N_) / 8, 256>>>(p_nt, p_nr, p_cand, p_idx);

        dim3 gQ(C_ / 128, (B_ * N_) / 128);
        sgemm_nn_128<<<gQ, 256>>>(cur, p_G, nullptr, p_q, B_ * N_, C_, C_);

        attn_kernel<<<B_ * N_, 128>>>(p_q, ref, p_idx, p_ctx);

        sgemm_nn_128<<<gQ, 256>>>(p_ctx, p_Wvo, cur, dst, B_ * N_, C_, C_);

        cur = p_slots;
    }
}

// round 12
// speedup vs baseline: 1.3949x; 1.3949x over previous
#include <cuda_runtime.h>
#include <cuda_bf16.h>
#include <math.h>
#include <stdint.h>

#define B_    8
#define N_    1024
#define M_    4096
#define C_    512
#define KNN   16
#define NCAND 32
#define ITERS 3

typedef __nv_bfloat16 bf16;

// ---------------- scratch (static device globals) ----------------
__device__ float g_nr   [(size_t)B_*M_*C_];
__device__ float g_nt   [(size_t)B_*N_*C_];
__device__ float g_corr [(size_t)B_*N_*M_];
__device__ float g_q    [(size_t)B_*N_*C_];
__device__ float g_ctx  [(size_t)B_*N_*C_];
__device__ float g_slots[(size_t)B_*N_*C_];
__device__ float g_G    [(size_t)C_*C_];     // Wq @ Wk^T
__device__ float g_Wvo  [(size_t)C_*C_];     // Wv @ Wo
__device__ bf16  g_nr_bf[(size_t)B_*M_*C_];
__device__ bf16  g_nt_bf[(size_t)B_*N_*C_];
__device__ int   g_cand [(size_t)B_*N_*NCAND];
__device__ int   g_idx  [(size_t)B_*N_*KNN];

// ---------------- MMA helpers (validated) ----------------
__device__ __forceinline__ uint32_t sptr(const void* p) {
    uint32_t r;
    asm("{ .reg .u64 t; cvta.to.shared.u64 t, %1; cvt.u32.u64 %0, t; }" : "=r"(r) : "l"(p));
    return r;
}
__device__ __forceinline__ void ldm_x4(uint32_t& r0, uint32_t& r1, uint32_t& r2, uint32_t& r3, uint32_t a) {
    asm volatile("ldmatrix.sync.aligned.m8n8.x4.shared.b16 {%0,%1,%2,%3}, [%4];"
                 : "=r"(r0), "=r"(r1), "=r"(r2), "=r"(r3) : "r"(a));
}
__device__ __forceinline__ void mma_bf16(float* c, const uint32_t* a, const uint32_t* b) {
    asm volatile("mma.sync.aligned.m16n8k16.row.col.f32.bf16.bf16.f32 "
                 "{%0,%1,%2,%3}, {%4,%5,%6,%7}, {%8,%9}, {%0,%1,%2,%3};"
                 : "+f"(c[0]), "+f"(c[1]), "+f"(c[2]), "+f"(c[3])
                 : "r"(a[0]), "r"(a[1]), "r"(a[2]), "r"(a[3]), "r"(b[0]), "r"(b[1]));
}
// swizzle for 128-byte rows, 8 chunks of 16B per row (conflict-free ldmatrix)
__device__ __forceinline__ uint32_t swz128(int row, int chunk) {
    return (uint32_t)(row * 128 + ((chunk ^ (row & 7)) << 4));
}

// ---------------- normalize rows + bf16 copy (validated) ----------------
__global__ void normalize_rows_bf(const float* __restrict__ x, float* __restrict__ y,
                                  bf16* __restrict__ ybf) {
    int row = blockIdx.x;
    const float4* xr = (const float4*)(x + (size_t)row * C_);
    float4 v = xr[threadIdx.x];
    float ss = v.x*v.x + v.y*v.y + v.z*v.z + v.w*v.w;
    #pragma unroll
    for (int o = 16; o; o >>= 1) ss += __shfl_down_sync(0xFFFFFFFFu, ss, o);
    __shared__ float red[4];
    if ((threadIdx.x & 31) == 0) red[threadIdx.x >> 5] = ss;
    __syncthreads();
    float tot = red[0] + red[1] + red[2] + red[3];
    float inv = 1.0f / sqrtf(tot);
    v.x *= inv; v.y *= inv; v.z *= inv; v.w *= inv;
    ((float4*)(y + (size_t)row * C_))[threadIdx.x] = v;
    __nv_bfloat162* o2 = (__nv_bfloat162*)(ybf + (size_t)row * C_);
    __nv_bfloat162 h0; h0.x = __float2bfloat16_rn(v.x); h0.y = __float2bfloat16_rn(v.y);
    __nv_bfloat162 h1; h1.x = __float2bfloat16_rn(v.z); h1.y = __float2bfloat16_rn(v.w);
    o2[threadIdx.x * 2] = h0; o2[threadIdx.x * 2 + 1] = h1;
}

// ---------------- corr GEMM: bf16 MMA, K-tile 64 (bitwise-identical k order) ----------
__global__ __launch_bounds__(256) void gemm_corr(const bf16* __restrict__ A,
                                                 const bf16* __restrict__ Bm,
                                                 float* __restrict__ C) {
    A  += (size_t)blockIdx.z * N_ * C_;
    Bm += (size_t)blockIdx.z * M_ * C_;
    C  += (size_t)blockIdx.z * N_ * M_;
    __shared__ __align__(16) uint8_t sA[128 * 128];   // 16 KB
    __shared__ __align__(16) uint8_t sB[128 * 128];   // 16 KB
    uint32_t baseA = sptr(sA), baseB = sptr(sB);
    int tid = threadIdx.x, lane = tid & 31, w = tid >> 5;
    int wm = w & 1, wn = w >> 1;
    int row0 = blockIdx.y * 128, col0 = blockIdx.x * 128;
    float acc[4][4][4] = {};
    for (int kt = 0; kt < C_ / 64; ++kt) {     // 8 k-tiles of 64
        int k0 = kt * 64;
        #pragma unroll
        for (int i = 0; i < 4; ++i) {
            int cid = tid + i * 256;           // 0..1023
            int r = cid >> 3, c = cid & 7;
            *(uint4*)(sA + swz128(r, c)) = *(const uint4*)(A + (size_t)(row0 + r) * C_ + k0 + c * 8);
            *(uint4*)(sB + swz128(r, c)) = *(const uint4*)(Bm + (size_t)(col0 + r) * C_ + k0 + c * 8);
        }
        __syncthreads();
        #pragma unroll
        for (int kk = 0; kk < 4; ++kk) {       // 4 x k16 per tile, ascending k
            uint32_t b[4][2];
            #pragma unroll
            for (int jn = 0; jn < 2; ++jn) {
                int r = wn * 32 + jn * 16 + (lane & 7) + ((lane >> 4) << 3);
                int ck = kk * 2 + ((lane >> 3) & 1);
                ldm_x4(b[jn*2][0], b[jn*2][1], b[jn*2+1][0], b[jn*2+1][1], baseB + swz128(r, ck));
            }
            #pragma unroll
            for (int im = 0; im < 4; ++im) {
                uint32_t a[4];
                int r = wm * 64 + im * 16 + (lane & 15);
                int ck = kk * 2 + (lane >> 4);
                ldm_x4(a[0], a[1], a[2], a[3], baseA + swz128(r, ck));
                #pragma unroll
                for (int in = 0; in < 4; ++in) mma_bf16(acc[im][in], a, b[in]);
            }
        }
        __syncthreads();
    }
    int g = lane >> 2, t2 = (lane & 3) * 2;
    #pragma unroll
    for (int im = 0; im < 4; ++im)
        #pragma unroll
        for (int in = 0; in < 4; ++in) {
            int row = row0 + wm * 64 + im * 16 + g;
            int col = col0 + wn * 32 + in * 8 + t2;
            *(float2*)(C + (size_t)row * M_ + col)       = make_float2(acc[im][in][0], acc[im][in][1]);
            *(float2*)(C + (size_t)(row + 8) * M_ + col) = make_float2(acc[im][in][2], acc[im][in][3]);
        }
}

// ---------------- approx top-32 candidates (R8 verbatim) ----------------
__global__ void cand32_kernel(const float* __restrict__ corr, int* __restrict__ out_idx) {
    int row  = blockIdx.x * (blockDim.x >> 5) + (threadIdx.x >> 5);
    int lane = threadIdx.x & 31;
    const float* cr = corr + (size_t)row * M_;
    float val[KNN];
    int   id [KNN];
    #pragma unroll
    for (int j = 0; j < KNN; ++j) { val[j] = -INFINITY; id[j] = 0x7FFFFFFF; }
    for (int m = lane; m < M_; m += 32) {
        float v = cr[m];
        if (v > val[KNN - 1]) {
            #pragma unroll
            for (int j = KNN - 1; j >= 0; --j) {
                bool shift = (j > 0) && (val[j - 1] < v);
                if (shift)            { val[j] = val[j - 1]; id[j] = id[j - 1]; }
                else if (val[j] < v)  { val[j] = v;          id[j] = m; }
            }
        }
    }
    int p = 0;
    for (int r = 0; r < NCAND; ++r) {
        float rv = (p < KNN) ? val[p] : -INFINITY;
        int   rm = (p < KNN) ? id[p]  : 0x7FFFFFFF;
        #pragma unroll
        for (int o = 16; o; o >>= 1) {
            float ov = __shfl_down_sync(0xFFFFFFFFu, rv, o);
            int   om = __shfl_down_sync(0xFFFFFFFFu, rm, o);
            if (ov > rv || (ov == rv && om < rm)) { rv = ov; rm = om; }
        }
        int wm = __shfl_sync(0xFFFFFFFFu, rm, 0);
        if (lane == 0) out_idx[(size_t)row * NCAND + r] = wm;
        if ((wm & 31) == lane) ++p;
    }
}

// ---------------- fp32 rescore (R8 verbatim: float4, sequential fmaf chain) ----------
__global__ void rescore_kernel(const float* __restrict__ nt, const float* __restrict__ nr,
                               const int* __restrict__ cand, int* __restrict__ out_idx) {
    int warp = threadIdx.x >> 5, lane = threadIdx.x & 31;
    int row = blockIdx.x * 8 + warp;
    int b = row >> 10;
    int cm = cand[(size_t)row * NCAND + lane];
    const float* q  = nt + (size_t)row * C_;
    const float* kr = nr + ((size_t)b * M_ + cm) * C_;
    float acc = 0.f;
    #pragma unroll 8
    for (int k = 0; k < C_; k += 4) {
        float4 qa = *(const float4*)(q + k);
        float4 ka = *(const float4*)(kr + k);
        acc = fmaf(qa.x, ka.x, acc);
        acc = fmaf(qa.y, ka.y, acc);
        acc = fmaf(qa.z, ka.z, acc);
        acc = fmaf(qa.w, ka.w, acc);
    }
    bool taken = false;
    for (int r = 0; r < KNN; ++r) {
        float rv = taken ? -INFINITY : acc;
        int   rm = taken ? 0x7FFFFFFF : cm;
        #pragma unroll
        for (int o = 16; o; o >>= 1) {
            float ov = __shfl_down_sync(0xFFFFFFFFu, rv, o);
            int   om = __shfl_down_sync(0xFFFFFFFFu, rm, o);
            if (ov > rv || (ov == rv && om < rm)) { rv = ov; rm = om; }
        }
        int wm = __shfl_sync(0xFFFFFFFFu, rm, 0);
        if (lane == 0) out_idx[(size_t)row * KNN + r] = wm;
        if (wm == cm) taken = true;
    }
}

// ======================= fp32 OUTPUT PATH (R8 verbatim) =======================

__global__ __launch_bounds__(256) void sgemm_nn_128(const float* __restrict__ A,
                                                    const float* __restrict__ W,
                                                    const float* __restrict__ R,
                                                    float* __restrict__ C,
                                                    int M, int N, int K) {
    __shared__ float As[16][128];
    __shared__ float Bs[16][128];
    int tid = threadIdx.x;
    int tx = tid & 15, ty = tid >> 4;
    int row0 = blockIdx.y * 128, col0 = blockIdx.x * 128;
    float acc[8][8] = {};
    for (int k0 = 0; k0 < K; k0 += 16) {
        #pragma unroll
        for (int i = 0; i < 2; ++i) {
            int chunk = tid * 2 + i;
            int r = chunk >> 2, kq = (chunk & 3) << 2;
            float4 v = *(const float4*)(A + (size_t)(row0 + r) * K + k0 + kq);
            As[kq + 0][r] = v.x; As[kq + 1][r] = v.y;
            As[kq + 2][r] = v.z; As[kq + 3][r] = v.w;
        }
        #pragma unroll
        for (int i = 0; i < 2; ++i) {
            int chunk = tid * 2 + i;
            int kr = chunk >> 5, c4 = (chunk & 31) << 2;
            *(float4*)&Bs[kr][c4] = *(const float4*)(W + (size_t)(k0 + kr) * N + col0 + c4);
        }
        __syncthreads();
        #pragma unroll
        for (int kk = 0; kk < 16; ++kk) {
            float a[8], b[8];
            *(float4*)(a)     = *(float4*)&As[kk][ty * 8];
            *(float4*)(a + 4) = *(float4*)&As[kk][ty * 8 + 4];
            *(float4*)(b)     = *(float4*)&Bs[kk][tx * 8];
            *(float4*)(b + 4) = *(float4*)&Bs[kk][tx * 8 + 4];
            #pragma unroll
            for (int i = 0; i < 8; ++i)
                #pragma unroll
                for (int j = 0; j < 8; ++j)
                    acc[i][j] = fmaf(a[i], b[j], acc[i][j]);
        }
        __syncthreads();
    }
    #pragma unroll
    for (int i = 0; i < 8; ++i) {
        int row = row0 + ty * 8 + i;
        #pragma unroll
        for (int j4 = 0; j4 < 2; ++j4) {
            int col = col0 + tx * 8 + j4 * 4;
            float4 o;
            o.x = acc[i][j4*4+0]; o.y = acc[i][j4*4+1];
            o.z = acc[i][j4*4+2]; o.w = acc[i][j4*4+3];
            if (R) {
                float4 r = *(const float4*)(R + (size_t)row * N + col);
                o.x += r.x; o.y += r.y; o.z += r.z; o.w += r.w;
            }
            *(float4*)(C + (size_t)row * N + col) = o;
        }
    }
}

#define BM 64
#define BN 64
#define BK 16
__global__ void sgemm_nn(const float* __restrict__ A, const float* __restrict__ W,
                         const float* __restrict__ R, float* __restrict__ C,
                         int M, int N, int K) {
    __shared__ float As[BK][BM];
    __shared__ float Bs[BK][BN];
    int tid = threadIdx.x;
    int tx = tid & 15, ty = tid >> 4;
    int row0 = blockIdx.y * BM, col0 = blockIdx.x * BN;
    float acc[4][4] = {};
    for (int k0 = 0; k0 < K; k0 += BK) {
        {
            int r = tid >> 2, kq = (tid & 3) << 2;
            float4 v = *(const float4*)(A + (size_t)(row0 + r) * K + k0 + kq);
            As[kq + 0][r] = v.x; As[kq + 1][r] = v.y;
            As[kq + 2][r] = v.z; As[kq + 3][r] = v.w;
        }
        {
            int r = tid >> 4, c = (tid & 15) << 2;
            *(float4*)&Bs[r][c] = *(const float4*)(W + (size_t)(k0 + r) * N + col0 + c);
        }
        __syncthreads();
        #pragma unroll
        for (int kk = 0; kk < BK; ++kk) {
            float a[4], b[4];
            *(float4*)a = *(float4*)&As[kk][ty << 2];
            *(float4*)b = *(float4*)&Bs[kk][tx << 2];
            #pragma unroll
            for (int i = 0; i < 4; ++i)
                #pragma unroll
                for (int j = 0; j < 4; ++j)
                    acc[i][j] += a[i] * b[j];
        }
        __syncthreads();
    }
    #pragma unroll
    for (int i = 0; i < 4; ++i) {
        int row = row0 + (ty << 2) + i;
        float4 o;
        o.x = acc[i][0]; o.y = acc[i][1]; o.z = acc[i][2]; o.w = acc[i][3];
        if (R) {
            float4 r = *(const float4*)(R + (size_t)row * N + col0 + (tx << 2));
            o.x += r.x; o.y += r.y; o.z += r.z; o.w += r.w;
        }
        *(float4*)(C + (size_t)row * N + col0 + (tx << 2)) = o;
    }
}

__global__ void sgemm_nt_w(const float* __restrict__ A, const float* __restrict__ Bm,
                           float* __restrict__ C) {
    __shared__ float As[BK][BM];
    __shared__ float Bs[BK][BN];
    int tid = threadIdx.x;
    int tx = tid & 15, ty = tid >> 4;
    int row0 = blockIdx.y * BM, col0 = blockIdx.x * BN;
    float acc[4][4] = {};
    for (int k0 = 0; k0 < C_; k0 += BK) {
        int r = tid >> 2, kq = (tid & 3) << 2;
        {
            float4 v = *(const float4*)(A + (size_t)(row0 + r) * C_ + k0 + kq);
            As[kq + 0][r] = v.x; As[kq + 1][r] = v.y;
            As[kq + 2][r] = v.z; As[kq + 3][r] = v.w;
        }
        {
            float4 v = *(const float4*)(Bm + (size_t)(col0 + r) * C_ + k0 + kq);
            Bs[kq + 0][r] = v.x; Bs[kq + 1][r] = v.y;
            Bs[kq + 2][r] = v.z; Bs[kq + 3][r] = v.w;
        }
        __syncthreads();
        #pragma unroll
        for (int kk = 0; kk < BK; ++kk) {
            float a[4], b[4];
            *(float4*)a = *(float4*)&As[kk][ty << 2];
            *(float4*)b = *(float4*)&Bs[kk][tx << 2];
            #pragma unroll
            for (int i = 0; i < 4; ++i)
                #pragma unroll
                for (int j = 0; j < 4; ++j)
                    acc[i][j] += a[i] * b[j];
        }
        __syncthreads();
    }
    #pragma unroll
    for (int i = 0; i < 4; ++i) {
        int row = row0 + (ty << 2) + i;
        float4 o;
        o.x = acc[i][0]; o.y = acc[i][1]; o.z = acc[i][2]; o.w = acc[i][3];
        *(float4*)(C + (size_t)row * C_ + col0 + (tx << 2)) = o;
    }
}

// ---------------- attention (R8 verbatim) ----------------
__global__ void attn_kernel(const float* __restrict__ q, const float* __restrict__ ref,
                            const int* __restrict__ idx, float* __restrict__ ctx) {
    int row = blockIdx.x, b = row >> 10;
    int tid = threadIdx.x, warp = tid >> 5, lane = tid & 31;
    __shared__ float s_logits[KNN];
    __shared__ int   s_idx[KNN];
    if (tid < KNN) s_idx[tid] = idx[(size_t)row * KNN + tid];
    __syncthreads();
    const float* qrow = q + (size_t)row * C_;
    const float scale = 0.04419417382415922f;   // 1/sqrt(512)
    #pragma unroll
    for (int j = 0; j < 4; ++j) {
        int kk = warp * 4 + j;
        const float* krow = ref + ((size_t)b * M_ + s_idx[kk]) * C_;
        float acc = 0.f;
        #pragma unroll
        for (int c = lane * 4; c < C_; c += 128) {
            float4 qa = *(const float4*)(qrow + c);
            float4 ka = *(const float4*)(krow + c);
            acc += qa.x * ka.x + qa.y * ka.y + qa.z * ka.z + qa.w * ka.w;
        }
        #pragma unroll
        for (int o = 16; o; o >>= 1) acc += __shfl_down_sync(0xFFFFFFFFu, acc, o);
        if (lane == 0) s_logits[kk] = acc * scale;
    }
    __syncthreads();
    float mx = -INFINITY;
    #pragma unroll
    for (int k = 0; k < KNN; ++k) mx = fmaxf(mx, s_logits[k]);
    float wv[KNN]; float wsum = 0.f;
    #pragma unroll
    for (int k = 0; k < KNN; ++k) { wv[k] = expf(s_logits[k] - mx); wsum += wv[k]; }
    float inv = 1.0f / wsum;
    int c = tid * 4;
    float4 acc4 = {0.f, 0.f, 0.f, 0.f};
    #pragma unroll
    for (int k = 0; k < KNN; ++k) {
        const float4 va = *(const float4*)(ref + ((size_t)b * M_ + s_idx[k]) * C_ + c);
        float wk = wv[k] * inv;
        acc4.x += wk * va.x; acc4.y += wk * va.y;
        acc4.z += wk * va.z; acc4.w += wk * va.w;
    }
    *(float4*)(ctx + (size_t)row * C_ + c) = acc4;
}

// ---------------- launch (R8 verbatim) ----------------
extern "C" void kernel_launch(void* const* d_in, const int* in_sizes, int n_in,
                              void* d_out, int out_size) {
    const float* slots_in = (const float*)d_in[0];
    const float* ref_list = (const float*)d_in[1];
    const float* Wq = (const float*)d_in[2];
    const float* Wk = (const float*)d_in[3];
    const float* Wv = (const float*)d_in[4];
    const float* Wo = (const float*)d_in[5];
    const float* ref = ref_list + ((size_t)in_sizes[1] - (size_t)B_ * M_ * C_);
    float* out = (float*)d_out;

    float *p_nr, *p_nt, *p_corr, *p_q, *p_ctx, *p_slots, *p_G, *p_Wvo;
    bf16 *p_nr_bf, *p_nt_bf;
    int *p_cand, *p_idx;
    cudaGetSymbolAddress((void**)&p_nr, g_nr);       cudaGetSymbolAddress((void**)&p_nt, g_nt);
    cudaGetSymbolAddress((void**)&p_corr, g_corr);   cudaGetSymbolAddress((void**)&p_q, g_q);
    cudaGetSymbolAddress((void**)&p_ctx, g_ctx);     cudaGetSymbolAddress((void**)&p_slots, g_slots);
    cudaGetSymbolAddress((void**)&p_G, g_G);         cudaGetSymbolAddress((void**)&p_Wvo, g_Wvo);
    cudaGetSymbolAddress((void**)&p_nr_bf, g_nr_bf); cudaGetSymbolAddress((void**)&p_nt_bf, g_nt_bf);
    cudaGetSymbolAddress((void**)&p_cand, g_cand);   cudaGetSymbolAddress((void**)&p_idx, g_idx);

    // ---- precompute ----
    normalize_rows_bf<<<B_ * M_, 128>>>(ref, p_nr, p_nr_bf);
    dim3 gW(C_ / BN, C_ / BM);
    sgemm_nt_w<<<gW, 256>>>(Wq, Wk, p_G);                        // G = Wq @ Wk^T
    sgemm_nn<<<gW, 256>>>(Wv, Wo, nullptr, p_Wvo, C_, C_, C_);   // Wvo = Wv @ Wo

    const float* cur = slots_in;
    for (int it = 0; it < ITERS; ++it) {
        float* dst = (it == ITERS - 1) ? out : p_slots;

        normalize_rows_bf<<<B_ * N_, 128>>>(cur, p_nt, p_nt_bf);

        dim3 gCorr(M_ / 128, N_ / 128, B_);
        gemm_corr<<<gCorr, 256>>>(p_nt_bf, p_nr_bf, p_corr);
        cand32_kernel<<<(B_ * N_) / 8, 256>>>(p_corr, p_cand);
        rescore_kernel<<<(B_ * N_) / 8, 256>>>(p_nt, p_nr, p_cand, p_idx);

        dim3 gQ(C_ / 128, (B_ * N_) / 128);
        sgemm_nn_128<<<gQ, 256>>>(cur, p_G, nullptr, p_q, B_ * N_, C_, C_);

        attn_kernel<<<B_ * N_, 128>>>(p_q, ref, p_idx, p_ctx);

        sgemm_nn_128<<<gQ, 256>>>(p_ctx, p_Wvo, cur, dst, B_ * N_, C_, C_);

        cur = p_slots;
    }
}

// round 13
// speedup vs baseline: 1.5518x; 1.1125x over previous
#include <cuda_runtime.h>
#include <cuda_bf16.h>
#include <math.h>
#include <stdint.h>

#define B_    8
#define N_    1024
#define M_    4096
#define C_    512
#define KNN   16
#define NCAND 24
#define ITERS 3

typedef __nv_bfloat16 bf16;

// ---------------- scratch (static device globals) ----------------
__device__ float g_nr   [(size_t)B_*M_*C_];
__device__ float g_nt   [(size_t)B_*N_*C_];
__device__ bf16  g_corr [(size_t)B_*N_*M_];   // bf16 candidate scores (64 MB)
__device__ float g_q    [(size_t)B_*N_*C_];
__device__ float g_ctx  [(size_t)B_*N_*C_];
__device__ float g_slots[(size_t)B_*N_*C_];
__device__ float g_G    [(size_t)C_*C_];      // Wq @ Wk^T
__device__ float g_Wvo  [(size_t)C_*C_];      // Wv @ Wo
__device__ bf16  g_nr_bf[(size_t)B_*M_*C_];
__device__ bf16  g_nt_bf[(size_t)B_*N_*C_];
__device__ int   g_cand [(size_t)B_*N_*NCAND];
__device__ int   g_idx  [(size_t)B_*N_*KNN];

// ---------------- MMA helpers (validated) ----------------
__device__ __forceinline__ uint32_t sptr(const void* p) {
    uint32_t r;
    asm("{ .reg .u64 t; cvta.to.shared.u64 t, %1; cvt.u32.u64 %0, t; }" : "=r"(r) : "l"(p));
    return r;
}
__device__ __forceinline__ void ldm_x4(uint32_t& r0, uint32_t& r1, uint32_t& r2, uint32_t& r3, uint32_t a) {
    asm volatile("ldmatrix.sync.aligned.m8n8.x4.shared.b16 {%0,%1,%2,%3}, [%4];"
                 : "=r"(r0), "=r"(r1), "=r"(r2), "=r"(r3) : "r"(a));
}
__device__ __forceinline__ void mma_bf16(float* c, const uint32_t* a, const uint32_t* b) {
    asm volatile("mma.sync.aligned.m16n8k16.row.col.f32.bf16.bf16.f32 "
                 "{%0,%1,%2,%3}, {%4,%5,%6,%7}, {%8,%9}, {%0,%1,%2,%3};"
                 : "+f"(c[0]), "+f"(c[1]), "+f"(c[2]), "+f"(c[3])
                 : "r"(a[0]), "r"(a[1]), "r"(a[2]), "r"(a[3]), "r"(b[0]), "r"(b[1]));
}
// swizzle for 128-byte rows, 8 chunks of 16B per row (conflict-free ldmatrix)
__device__ __forceinline__ uint32_t swz128(int row, int chunk) {
    return (uint32_t)(row * 128 + ((chunk ^ (row & 7)) << 4));
}

// ---------------- normalize rows + bf16 copy (validated) ----------------
__global__ void normalize_rows_bf(const float* __restrict__ x, float* __restrict__ y,
                                  bf16* __restrict__ ybf) {
    int row = blockIdx.x;
    const float4* xr = (const float4*)(x + (size_t)row * C_);
    float4 v = xr[threadIdx.x];
    float ss = v.x*v.x + v.y*v.y + v.z*v.z + v.w*v.w;
    #pragma unroll
    for (int o = 16; o; o >>= 1) ss += __shfl_down_sync(0xFFFFFFFFu, ss, o);
    __shared__ float red[4];
    if ((threadIdx.x & 31) == 0) red[threadIdx.x >> 5] = ss;
    __syncthreads();
    float tot = red[0] + red[1] + red[2] + red[3];
    float inv = 1.0f / sqrtf(tot);
    v.x *= inv; v.y *= inv; v.z *= inv; v.w *= inv;
    ((float4*)(y + (size_t)row * C_))[threadIdx.x] = v;
    __nv_bfloat162* o2 = (__nv_bfloat162*)(ybf + (size_t)row * C_);
    __nv_bfloat162 h0; h0.x = __float2bfloat16_rn(v.x); h0.y = __float2bfloat16_rn(v.y);
    __nv_bfloat162 h1; h1.x = __float2bfloat16_rn(v.z); h1.y = __float2bfloat16_rn(v.w);
    o2[threadIdx.x * 2] = h0; o2[threadIdx.x * 2 + 1] = h1;
}

// ---------------- corr GEMM: bf16 MMA, K-tile 64, bf16 score output ----------
__global__ __launch_bounds__(256) void gemm_corr(const bf16* __restrict__ A,
                                                 const bf16* __restrict__ Bm,
                                                 bf16* __restrict__ C) {
    A  += (size_t)blockIdx.z * N_ * C_;
    Bm += (size_t)blockIdx.z * M_ * C_;
    C  += (size_t)blockIdx.z * N_ * M_;
    __shared__ __align__(16) uint8_t sA[128 * 128];   // 16 KB
    __shared__ __align__(16) uint8_t sB[128 * 128];   // 16 KB
    uint32_t baseA = sptr(sA), baseB = sptr(sB);
    int tid = threadIdx.x, lane = tid & 31, w = tid >> 5;
    int wm = w & 1, wn = w >> 1;
    int row0 = blockIdx.y * 128, col0 = blockIdx.x * 128;
    float acc[4][4][4] = {};
    for (int kt = 0; kt < C_ / 64; ++kt) {     // 8 k-tiles of 64
        int k0 = kt * 64;
        #pragma unroll
        for (int i = 0; i < 4; ++i) {
            int cid = tid + i * 256;           // 0..1023
            int r = cid >> 3, c = cid & 7;
            *(uint4*)(sA + swz128(r, c)) = *(const uint4*)(A + (size_t)(row0 + r) * C_ + k0 + c * 8);
            *(uint4*)(sB + swz128(r, c)) = *(const uint4*)(Bm + (size_t)(col0 + r) * C_ + k0 + c * 8);
        }
        __syncthreads();
        #pragma unroll
        for (int kk = 0; kk < 4; ++kk) {       // 4 x k16 per tile, ascending k
            uint32_t b[4][2];
            #pragma unroll
            for (int jn = 0; jn < 2; ++jn) {
                int r = wn * 32 + jn * 16 + (lane & 7) + ((lane >> 4) << 3);
                int ck = kk * 2 + ((lane >> 3) & 1);
                ldm_x4(b[jn*2][0], b[jn*2][1], b[jn*2+1][0], b[jn*2+1][1], baseB + swz128(r, ck));
            }
            #pragma unroll
            for (int im = 0; im < 4; ++im) {
                uint32_t a[4];
                int r = wm * 64 + im * 16 + (lane & 15);
                int ck = kk * 2 + (lane >> 4);
                ldm_x4(a[0], a[1], a[2], a[3], baseA + swz128(r, ck));
                #pragma unroll
                for (int in = 0; in < 4; ++in) mma_bf16(acc[im][in], a, b[in]);
            }
        }
        __syncthreads();
    }
    int g = lane >> 2, t2 = (lane & 3) * 2;
    #pragma unroll
    for (int im = 0; im < 4; ++im)
        #pragma unroll
        for (int in = 0; in < 4; ++in) {
            int row = row0 + wm * 64 + im * 16 + g;
            int col = col0 + wn * 32 + in * 8 + t2;
            __nv_bfloat162 p0, p1;
            p0.x = __float2bfloat16_rn(acc[im][in][0]); p0.y = __float2bfloat16_rn(acc[im][in][1]);
            p1.x = __float2bfloat16_rn(acc[im][in][2]); p1.y = __float2bfloat16_rn(acc[im][in][3]);
            *(__nv_bfloat162*)(C + (size_t)row * M_ + col)       = p0;
            *(__nv_bfloat162*)(C + (size_t)(row + 8) * M_ + col) = p1;
        }
}

// ---------------- approx top-24 candidates from bf16 scores ----------------
__global__ void cand_kernel(const bf16* __restrict__ corr, int* __restrict__ out_idx) {
    int row  = blockIdx.x * (blockDim.x >> 5) + (threadIdx.x >> 5);
    int lane = threadIdx.x & 31;
    const bf16* cr = corr + (size_t)row * M_;
    float val[KNN];
    int   id [KNN];
    #pragma unroll
    for (int j = 0; j < KNN; ++j) { val[j] = -INFINITY; id[j] = 0x7FFFFFFF; }
    for (int m = lane; m < M_; m += 32) {
        float v = __bfloat162float(cr[m]);
        if (v > val[KNN - 1]) {
            #pragma unroll
            for (int j = KNN - 1; j >= 0; --j) {
                bool shift = (j > 0) && (val[j - 1] < v);
                if (shift)            { val[j] = val[j - 1]; id[j] = id[j - 1]; }
                else if (val[j] < v)  { val[j] = v;          id[j] = m; }
            }
        }
    }
    int p = 0;
    for (int r = 0; r < NCAND; ++r) {
        float rv = (p < KNN) ? val[p] : -INFINITY;
        int   rm = (p < KNN) ? id[p]  : 0x7FFFFFFF;
        #pragma unroll
        for (int o = 16; o; o >>= 1) {
            float ov = __shfl_down_sync(0xFFFFFFFFu, rv, o);
            int   om = __shfl_down_sync(0xFFFFFFFFu, rm, o);
            if (ov > rv || (ov == rv && om < rm)) { rv = ov; rm = om; }
        }
        int wm = __shfl_sync(0xFFFFFFFFu, rm, 0);
        if (lane == 0) out_idx[(size_t)row * NCAND + r] = wm;
        if ((wm & 31) == lane && p < KNN && id[p] == wm) ++p;
    }
}

// ---------------- fp32 rescore of 24 candidates (exact sequential fmaf chain) ---------
__global__ void rescore_kernel(const float* __restrict__ nt, const float* __restrict__ nr,
                               const int* __restrict__ cand, int* __restrict__ out_idx) {
    int warp = threadIdx.x >> 5, lane = threadIdx.x & 31;
    int row = blockIdx.x * 8 + warp;
    int b = row >> 10;
    bool valid = lane < NCAND;
    int cm = valid ? cand[(size_t)row * NCAND + lane] : 0x7FFFFFFF;
    const float* q  = nt + (size_t)row * C_;
    const float* kr = nr + ((size_t)b * M_ + (valid ? cm : 0)) * C_;
    float acc = 0.f;
    #pragma unroll 8
    for (int k = 0; k < C_; k += 4) {
        float4 qa = *(const float4*)(q + k);
        float4 ka = *(const float4*)(kr + k);
        acc = fmaf(qa.x, ka.x, acc);
        acc = fmaf(qa.y, ka.y, acc);
        acc = fmaf(qa.z, ka.z, acc);
        acc = fmaf(qa.w, ka.w, acc);
    }
    if (!valid) acc = -INFINITY;
    bool taken = false;
    for (int r = 0; r < KNN; ++r) {
        float rv = (taken || !valid) ? -INFINITY : acc;
        int   rm = (taken || !valid) ? 0x7FFFFFFF : cm;
        #pragma unroll
        for (int o = 16; o; o >>= 1) {
            float ov = __shfl_down_sync(0xFFFFFFFFu, rv, o);
            int   om = __shfl_down_sync(0xFFFFFFFFu, rm, o);
            if (ov > rv || (ov == rv && om < rm)) { rv = ov; rm = om; }
        }
        int wm = __shfl_sync(0xFFFFFFFFu, rm, 0);
        if (lane == 0) out_idx[(size_t)row * KNN + r] = wm;
        if (wm == cm) taken = true;
    }
}

// ======================= fp32 OUTPUT PATH (R8/R12 verbatim) =======================

__global__ __launch_bounds__(256) void sgemm_nn_128(const float* __restrict__ A,
                                                    const float* __restrict__ W,
                                                    const float* __restrict__ R,
                                                    float* __restrict__ C,
                                                    int M, int N, int K) {
    __shared__ float As[16][128];
    __shared__ float Bs[16][128];
    int tid = threadIdx.x;
    int tx = tid & 15, ty = tid >> 4;
    int row0 = blockIdx.y * 128, col0 = blockIdx.x * 128;
    float acc[8][8] = {};
    for (int k0 = 0; k0 < K; k0 += 16) {
        #pragma unroll
        for (int i = 0; i < 2; ++i) {
            int chunk = tid * 2 + i;
            int r = chunk >> 2, kq = (chunk & 3) << 2;
            float4 v = *(const float4*)(A + (size_t)(row0 + r) * K + k0 + kq);
            As[kq + 0][r] = v.x; As[kq + 1][r] = v.y;
            As[kq + 2][r] = v.z; As[kq + 3][r] = v.w;
        }
        #pragma unroll
        for (int i = 0; i < 2; ++i) {
            int chunk = tid * 2 + i;
            int kr = chunk >> 5, c4 = (chunk & 31) << 2;
            *(float4*)&Bs[kr][c4] = *(const float4*)(W + (size_t)(k0 + kr) * N + col0 + c4);
        }
        __syncthreads();
        #pragma unroll
        for (int kk = 0; kk < 16; ++kk) {
            float a[8], b[8];
            *(float4*)(a)     = *(float4*)&As[kk][ty * 8];
            *(float4*)(a + 4) = *(float4*)&As[kk][ty * 8 + 4];
            *(float4*)(b)     = *(float4*)&Bs[kk][tx * 8];
            *(float4*)(b + 4) = *(float4*)&Bs[kk][tx * 8 + 4];
            #pragma unroll
            for (int i = 0; i < 8; ++i)
                #pragma unroll
                for (int j = 0; j < 8; ++j)
                    acc[i][j] = fmaf(a[i], b[j], acc[i][j]);
        }
        __syncthreads();
    }
    #pragma unroll
    for (int i = 0; i < 8; ++i) {
        int row = row0 + ty * 8 + i;
        #pragma unroll
        for (int j4 = 0; j4 < 2; ++j4) {
            int col = col0 + tx * 8 + j4 * 4;
            float4 o;
            o.x = acc[i][j4*4+0]; o.y = acc[i][j4*4+1];
            o.z = acc[i][j4*4+2]; o.w = acc[i][j4*4+3];
            if (R) {
                float4 r = *(const float4*)(R + (size_t)row * N + col);
                o.x += r.x; o.y += r.y; o.z += r.z; o.w += r.w;
            }
            *(float4*)(C + (size_t)row * N + col) = o;
        }
    }
}

#define BM 64
#define BN 64
#define BK 16
__global__ void sgemm_nn(const float* __restrict__ A, const float* __restrict__ W,
                         const float* __restrict__ R, float* __restrict__ C,
                         int M, int N, int K) {
    __shared__ float As[BK][BM];
    __shared__ float Bs[BK][BN];
    int tid = threadIdx.x;
    int tx = tid & 15, ty = tid >> 4;
    int row0 = blockIdx.y * BM, col0 = blockIdx.x * BN;
    float acc[4][4] = {};
    for (int k0 = 0; k0 < K; k0 += BK) {
        {
            int r = tid >> 2, kq = (tid & 3) << 2;
            float4 v = *(const float4*)(A + (size_t)(row0 + r) * K + k0 + kq);
            As[kq + 0][r] = v.x; As[kq + 1][r] = v.y;
            As[kq + 2][r] = v.z; As[kq + 3][r] = v.w;
        }
        {
            int r = tid >> 4, c = (tid & 15) << 2;
            *(float4*)&Bs[r][c] = *(const float4*)(W + (size_t)(k0 + r) * N + col0 + c);
        }
        __syncthreads();
        #pragma unroll
        for (int kk = 0; kk < BK; ++kk) {
            float a[4], b[4];
            *(float4*)a = *(float4*)&As[kk][ty << 2];
            *(float4*)b = *(float4*)&Bs[kk][tx << 2];
            #pragma unroll
            for (int i = 0; i < 4; ++i)
                #pragma unroll
                for (int j = 0; j < 4; ++j)
                    acc[i][j] += a[i] * b[j];
        }
        __syncthreads();
    }
    #pragma unroll
    for (int i = 0; i < 4; ++i) {
        int row = row0 + (ty << 2) + i;
        float4 o;
        o.x = acc[i][0]; o.y = acc[i][1]; o.z = acc[i][2]; o.w = acc[i][3];
        if (R) {
            float4 r = *(const float4*)(R + (size_t)row * N + col0 + (tx << 2));
            o.x += r.x; o.y += r.y; o.z += r.z; o.w += r.w;
        }
        *(float4*)(C + (size_t)row * N + col0 + (tx << 2)) = o;
    }
}

__global__ void sgemm_nt_w(const float* __restrict__ A, const float* __restrict__ Bm,
                           float* __restrict__ C) {
    __shared__ float As[BK][BM];
    __shared__ float Bs[BK][BN];
    int tid = threadIdx.x;
    int tx = tid & 15, ty = tid >> 4;
    int row0 = blockIdx.y * BM, col0 = blockIdx.x * BN;
    float acc[4][4] = {};
    for (int k0 = 0; k0 < C_; k0 += BK) {
        int r = tid >> 2, kq = (tid & 3) << 2;
        {
            float4 v = *(const float4*)(A + (size_t)(row0 + r) * C_ + k0 + kq);
            As[kq + 0][r] = v.x; As[kq + 1][r] = v.y;
            As[kq + 2][r] = v.z; As[kq + 3][r] = v.w;
        }
        {
            float4 v = *(const float4*)(Bm + (size_t)(col0 + r) * C_ + k0 + kq);
            Bs[kq + 0][r] = v.x; Bs[kq + 1][r] = v.y;
            Bs[kq + 2][r] = v.z; Bs[kq + 3][r] = v.w;
        }
        __syncthreads();
        #pragma unroll
        for (int kk = 0; kk < BK; ++kk) {
            float a[4], b[4];
            *(float4*)a = *(float4*)&As[kk][ty << 2];
            *(float4*)b = *(float4*)&Bs[kk][tx << 2];
            #pragma unroll
            for (int i = 0; i < 4; ++i)
                #pragma unroll
                for (int j = 0; j < 4; ++j)
                    acc[i][j] += a[i] * b[j];
        }
        __syncthreads();
    }
    #pragma unroll
    for (int i = 0; i < 4; ++i) {
        int row = row0 + (ty << 2) + i;
        float4 o;
        o.x = acc[i][0]; o.y = acc[i][1]; o.z = acc[i][2]; o.w = acc[i][3];
        *(float4*)(C + (size_t)row * C_ + col0 + (tx << 2)) = o;
    }
}

// ---------------- attention (R8 verbatim) ----------------
__global__ void attn_kernel(const float* __restrict__ q, const float* __restrict__ ref,
                            const int* __restrict__ idx, float* __restrict__ ctx) {
    int row = blockIdx.x, b = row >> 10;
    int tid = threadIdx.x, warp = tid >> 5, lane = tid & 31;
    __shared__ float s_logits[KNN];
    __shared__ int   s_idx[KNN];
    if (tid < KNN) s_idx[tid] = idx[(size_t)row * KNN + tid];
    __syncthreads();
    const float* qrow = q + (size_t)row * C_;
    const float scale = 0.04419417382415922f;   // 1/sqrt(512)
    #pragma unroll
    for (int j = 0; j < 4; ++j) {
        int kk = warp * 4 + j;
        const float* krow = ref + ((size_t)b * M_ + s_idx[kk]) * C_;
        float acc = 0.f;
        #pragma unroll
        for (int c = lane * 4; c < C_; c += 128) {
            float4 qa = *(const float4*)(qrow + c);
            float4 ka = *(const float4*)(krow + c);
            acc += qa.x * ka.x + qa.y * ka.y + qa.z * ka.z + qa.w * ka.w;
        }
        #pragma unroll
        for (int o = 16; o; o >>= 1) acc += __shfl_down_sync(0xFFFFFFFFu, acc, o);
        if (lane == 0) s_logits[kk] = acc * scale;
    }
    __syncthreads();
    float mx = -INFINITY;
    #pragma unroll
    for (int k = 0; k < KNN; ++k) mx = fmaxf(mx, s_logits[k]);
    float wv[KNN]; float wsum = 0.f;
    #pragma unroll
    for (int k = 0; k < KNN; ++k) { wv[k] = expf(s_logits[k] - mx); wsum += wv[k]; }
    float inv = 1.0f / wsum;
    int c = tid * 4;
    float4 acc4 = {0.f, 0.f, 0.f, 0.f};
    #pragma unroll
    for (int k = 0; k < KNN; ++k) {
        const float4 va = *(const float4*)(ref + ((size_t)b * M_ + s_idx[k]) * C_ + c);
        float wk = wv[k] * inv;
        acc4.x += wk * va.x; acc4.y += wk * va.y;
        acc4.z += wk * va.z; acc4.w += wk * va.w;
    }
    *(float4*)(ctx + (size_t)row * C_ + c) = acc4;
}

// ---------------- launch (R12 verbatim schedule) ----------------
extern "C" void kernel_launch(void* const* d_in, const int* in_sizes, int n_in,
                              void* d_out, int out_size) {
    const float* slots_in = (const float*)d_in[0];
    const float* ref_list = (const float*)d_in[1];
    const float* Wq = (const float*)d_in[2];
    const float* Wk = (const float*)d_in[3];
    const float* Wv = (const float*)d_in[4];
    const float* Wo = (const float*)d_in[5];
    const float* ref = ref_list + ((size_t)in_sizes[1] - (size_t)B_ * M_ * C_);
    float* out = (float*)d_out;

    float *p_nr, *p_nt, *p_q, *p_ctx, *p_slots, *p_G, *p_Wvo;
    bf16 *p_corr, *p_nr_bf, *p_nt_bf;
    int *p_cand, *p_idx;
    cudaGetSymbolAddress((void**)&p_nr, g_nr);       cudaGetSymbolAddress((void**)&p_nt, g_nt);
    cudaGetSymbolAddress((void**)&p_corr, g_corr);   cudaGetSymbolAddress((void**)&p_q, g_q);
    cudaGetSymbolAddress((void**)&p_ctx, g_ctx);     cudaGetSymbolAddress((void**)&p_slots, g_slots);
    cudaGetSymbolAddress((void**)&p_G, g_G);         cudaGetSymbolAddress((void**)&p_Wvo, g_Wvo);
    cudaGetSymbolAddress((void**)&p_nr_bf, g_nr_bf); cudaGetSymbolAddress((void**)&p_nt_bf, g_nt_bf);
    cudaGetSymbolAddress((void**)&p_cand, g_cand);   cudaGetSymbolAddress((void**)&p_idx, g_idx);

    // ---- precompute ----
    normalize_rows_bf<<<B_ * M_, 128>>>(ref, p_nr, p_nr_bf);
    dim3 gW(C_ / BN, C_ / BM);
    sgemm_nt_w<<<gW, 256>>>(Wq, Wk, p_G);                        // G = Wq @ Wk^T
    sgemm_nn<<<gW, 256>>>(Wv, Wo, nullptr, p_Wvo, C_, C_, C_);   // Wvo = Wv @ Wo

    const float* cur = slots_in;
    for (int it = 0; it < ITERS; ++it) {
        float* dst = (it == ITERS - 1) ? out : p_slots;

        normalize_rows_bf<<<B_ * N_, 128>>>(cur, p_nt, p_nt_bf);

        dim3 gCorr(M_ / 128, N_ / 128, B_);
        gemm_corr<<<gCorr, 256>>>(p_nt_bf, p_nr_bf, p_corr);
        cand_kernel<<<(B_ * N_) / 8, 256>>>(p_corr, p_cand);
        rescore_kernel<<<(B_ * N_) / 8, 256>>>(p_nt, p_nr, p_cand, p_idx);

        dim3 gQ(C_ / 128, (B_ * N_) / 128);
        sgemm_nn_128<<<gQ, 256>>>(cur, p_G, nullptr, p_q, B_ * N_, C_, C_);

        attn_kernel<<<B_ * N_, 128>>>(p_q, ref, p_idx, p_ctx);

        sgemm_nn_128<<<gQ, 256>>>(p_ctx, p_Wvo, cur, dst, B_ * N_, C_, C_);

        cur = p_slots;
    }
}

// round 14
// speedup vs baseline: 1.5756x; 1.0153x over previous
#include <cuda_runtime.h>
#include <cuda_bf16.h>
#include <math.h>
#include <stdint.h>

#define B_    8
#define N_    1024
#define M_    4096
#define C_    512
#define KNN   16
#define NCAND 24
#define ITERS 3

typedef __nv_bfloat16 bf16;

// ---------------- scratch (static device globals) ----------------
__device__ float g_nr   [(size_t)B_*M_*C_];
__device__ float g_nt   [(size_t)B_*N_*C_];
__device__ bf16  g_corr [(size_t)B_*N_*M_];   // bf16 candidate scores (64 MB)
__device__ float g_q    [(size_t)B_*N_*C_];
__device__ float g_ctx  [(size_t)B_*N_*C_];
__device__ float g_slots[(size_t)B_*N_*C_];
__device__ float g_G    [(size_t)C_*C_];      // Wq @ Wk^T
__device__ float g_Wvo  [(size_t)C_*C_];      // Wv @ Wo
__device__ bf16  g_nr_bf[(size_t)B_*M_*C_];
__device__ bf16  g_nt_bf[(size_t)B_*N_*C_];
__device__ int   g_cand [(size_t)B_*N_*NCAND];
__device__ int   g_idx  [(size_t)B_*N_*KNN];

// ---------------- MMA helpers (validated) ----------------
__device__ __forceinline__ uint32_t sptr(const void* p) {
    uint32_t r;
    asm("{ .reg .u64 t; cvta.to.shared.u64 t, %1; cvt.u32.u64 %0, t; }" : "=r"(r) : "l"(p));
    return r;
}
__device__ __forceinline__ void ldm_x4(uint32_t& r0, uint32_t& r1, uint32_t& r2, uint32_t& r3, uint32_t a) {
    asm volatile("ldmatrix.sync.aligned.m8n8.x4.shared.b16 {%0,%1,%2,%3}, [%4];"
                 : "=r"(r0), "=r"(r1), "=r"(r2), "=r"(r3) : "r"(a));
}
__device__ __forceinline__ void mma_bf16(float* c, const uint32_t* a, const uint32_t* b) {
    asm volatile("mma.sync.aligned.m16n8k16.row.col.f32.bf16.bf16.f32 "
                 "{%0,%1,%2,%3}, {%4,%5,%6,%7}, {%8,%9}, {%0,%1,%2,%3};"
                 : "+f"(c[0]), "+f"(c[1]), "+f"(c[2]), "+f"(c[3])
                 : "r"(a[0]), "r"(a[1]), "r"(a[2]), "r"(a[3]), "r"(b[0]), "r"(b[1]));
}
// swizzle for 128-byte rows, 8 chunks of 16B per row (conflict-free ldmatrix)
__device__ __forceinline__ uint32_t swz128(int row, int chunk) {
    return (uint32_t)(row * 128 + ((chunk ^ (row & 7)) << 4));
}

// ---------------- normalize rows + bf16 copy (validated) ----------------
__global__ void normalize_rows_bf(const float* __restrict__ x, float* __restrict__ y,
                                  bf16* __restrict__ ybf) {
    int row = blockIdx.x;
    const float4* xr = (const float4*)(x + (size_t)row * C_);
    float4 v = xr[threadIdx.x];
    float ss = v.x*v.x + v.y*v.y + v.z*v.z + v.w*v.w;
    #pragma unroll
    for (int o = 16; o; o >>= 1) ss += __shfl_down_sync(0xFFFFFFFFu, ss, o);
    __shared__ float red[4];
    if ((threadIdx.x & 31) == 0) red[threadIdx.x >> 5] = ss;
    __syncthreads();
    float tot = red[0] + red[1] + red[2] + red[3];
    float inv = 1.0f / sqrtf(tot);
    v.x *= inv; v.y *= inv; v.z *= inv; v.w *= inv;
    ((float4*)(y + (size_t)row * C_))[threadIdx.x] = v;
    __nv_bfloat162* o2 = (__nv_bfloat162*)(ybf + (size_t)row * C_);
    __nv_bfloat162 h0; h0.x = __float2bfloat16_rn(v.x); h0.y = __float2bfloat16_rn(v.y);
    __nv_bfloat162 h1; h1.x = __float2bfloat16_rn(v.z); h1.y = __float2bfloat16_rn(v.w);
    o2[threadIdx.x * 2] = h0; o2[threadIdx.x * 2 + 1] = h1;
}

// ---------------- corr GEMM: bf16 MMA, K-tile 64, bf16 score output (validated) --------
__global__ __launch_bounds__(256) void gemm_corr(const bf16* __restrict__ A,
                                                 const bf16* __restrict__ Bm,
                                                 bf16* __restrict__ C) {
    A  += (size_t)blockIdx.z * N_ * C_;
    Bm += (size_t)blockIdx.z * M_ * C_;
    C  += (size_t)blockIdx.z * N_ * M_;
    __shared__ __align__(16) uint8_t sA[128 * 128];   // 16 KB
    __shared__ __align__(16) uint8_t sB[128 * 128];   // 16 KB
    uint32_t baseA = sptr(sA), baseB = sptr(sB);
    int tid = threadIdx.x, lane = tid & 31, w = tid >> 5;
    int wm = w & 1, wn = w >> 1;
    int row0 = blockIdx.y * 128, col0 = blockIdx.x * 128;
    float acc[4][4][4] = {};
    for (int kt = 0; kt < C_ / 64; ++kt) {     // 8 k-tiles of 64
        int k0 = kt * 64;
        #pragma unroll
        for (int i = 0; i < 4; ++i) {
            int cid = tid + i * 256;           // 0..1023
            int r = cid >> 3, c = cid & 7;
            *(uint4*)(sA + swz128(r, c)) = *(const uint4*)(A + (size_t)(row0 + r) * C_ + k0 + c * 8);
            *(uint4*)(sB + swz128(r, c)) = *(const uint4*)(Bm + (size_t)(col0 + r) * C_ + k0 + c * 8);
        }
        __syncthreads();
        #pragma unroll
        for (int kk = 0; kk < 4; ++kk) {       // 4 x k16 per tile, ascending k
            uint32_t b[4][2];
            #pragma unroll
            for (int jn = 0; jn < 2; ++jn) {
                int r = wn * 32 + jn * 16 + (lane & 7) + ((lane >> 4) << 3);
                int ck = kk * 2 + ((lane >> 3) & 1);
                ldm_x4(b[jn*2][0], b[jn*2][1], b[jn*2+1][0], b[jn*2+1][1], baseB + swz128(r, ck));
            }
            #pragma unroll
            for (int im = 0; im < 4; ++im) {
                uint32_t a[4];
                int r = wm * 64 + im * 16 + (lane & 15);
                int ck = kk * 2 + (lane >> 4);
                ldm_x4(a[0], a[1], a[2], a[3], baseA + swz128(r, ck));
                #pragma unroll
                for (int in = 0; in < 4; ++in) mma_bf16(acc[im][in], a, b[in]);
            }
        }
        __syncthreads();
    }
    int g = lane >> 2, t2 = (lane & 3) * 2;
    #pragma unroll
    for (int im = 0; im < 4; ++im)
        #pragma unroll
        for (int in = 0; in < 4; ++in) {
            int row = row0 + wm * 64 + im * 16 + g;
            int col = col0 + wn * 32 + in * 8 + t2;
            __nv_bfloat162 p0, p1;
            p0.x = __float2bfloat16_rn(acc[im][in][0]); p0.y = __float2bfloat16_rn(acc[im][in][1]);
            p1.x = __float2bfloat16_rn(acc[im][in][2]); p1.y = __float2bfloat16_rn(acc[im][in][3]);
            *(__nv_bfloat162*)(C + (size_t)row * M_ + col)       = p0;
            *(__nv_bfloat162*)(C + (size_t)(row + 8) * M_ + col) = p1;
        }
}

// ---------------- approx top-24 candidates from bf16 scores (validated) ----------------
__global__ void cand_kernel(const bf16* __restrict__ corr, int* __restrict__ out_idx) {
    int row  = blockIdx.x * (blockDim.x >> 5) + (threadIdx.x >> 5);
    int lane = threadIdx.x & 31;
    const bf16* cr = corr + (size_t)row * M_;
    float val[KNN];
    int   id [KNN];
    #pragma unroll
    for (int j = 0; j < KNN; ++j) { val[j] = -INFINITY; id[j] = 0x7FFFFFFF; }
    for (int m = lane; m < M_; m += 32) {
        float v = __bfloat162float(cr[m]);
        if (v > val[KNN - 1]) {
            #pragma unroll
            for (int j = KNN - 1; j >= 0; --j) {
                bool shift = (j > 0) && (val[j - 1] < v);
                if (shift)            { val[j] = val[j - 1]; id[j] = id[j - 1]; }
                else if (val[j] < v)  { val[j] = v;          id[j] = m; }
            }
        }
    }
    int p = 0;
    for (int r = 0; r < NCAND; ++r) {
        float rv = (p < KNN) ? val[p] : -INFINITY;
        int   rm = (p < KNN) ? id[p]  : 0x7FFFFFFF;
        #pragma unroll
        for (int o = 16; o; o >>= 1) {
            float ov = __shfl_down_sync(0xFFFFFFFFu, rv, o);
            int   om = __shfl_down_sync(0xFFFFFFFFu, rm, o);
            if (ov > rv || (ov == rv && om < rm)) { rv = ov; rm = om; }
        }
        int wm = __shfl_sync(0xFFFFFFFFu, rm, 0);
        if (lane == 0) out_idx[(size_t)row * NCAND + r] = wm;
        if ((wm & 31) == lane && p < KNN && id[p] == wm) ++p;
    }
}

// ---------------- fp32 rescore of 24 candidates (validated) ----------
__global__ void rescore_kernel(const float* __restrict__ nt, const float* __restrict__ nr,
                               const int* __restrict__ cand, int* __restrict__ out_idx) {
    int warp = threadIdx.x >> 5, lane = threadIdx.x & 31;
    int row = blockIdx.x * 8 + warp;
    int b = row >> 10;
    bool valid = lane < NCAND;
    int cm = valid ? cand[(size_t)row * NCAND + lane] : 0x7FFFFFFF;
    const float* q  = nt + (size_t)row * C_;
    const float* kr = nr + ((size_t)b * M_ + (valid ? cm : 0)) * C_;
    float acc = 0.f;
    #pragma unroll 8
    for (int k = 0; k < C_; k += 4) {
        float4 qa = *(const float4*)(q + k);
        float4 ka = *(const float4*)(kr + k);
        acc = fmaf(qa.x, ka.x, acc);
        acc = fmaf(qa.y, ka.y, acc);
        acc = fmaf(qa.z, ka.z, acc);
        acc = fmaf(qa.w, ka.w, acc);
    }
    if (!valid) acc = -INFINITY;
    bool taken = false;
    for (int r = 0; r < KNN; ++r) {
        float rv = (taken || !valid) ? -INFINITY : acc;
        int   rm = (taken || !valid) ? 0x7FFFFFFF : cm;
        #pragma unroll
        for (int o = 16; o; o >>= 1) {
            float ov = __shfl_down_sync(0xFFFFFFFFu, rv, o);
            int   om = __shfl_down_sync(0xFFFFFFFFu, rm, o);
            if (ov > rv || (ov == rv && om < rm)) { rv = ov; rm = om; }
        }
        int wm = __shfl_sync(0xFFFFFFFFu, rm, 0);
        if (lane == 0) out_idx[(size_t)row * KNN + r] = wm;
        if (wm == cm) taken = true;
    }
}

// ======================= fp32 OUTPUT PATH (validated) =======================

__global__ __launch_bounds__(256) void sgemm_nn_128(const float* __restrict__ A,
                                                    const float* __restrict__ W,
                                                    const float* __restrict__ R,
                                                    float* __restrict__ C,
                                                    int M, int N, int K) {
    __shared__ float As[16][128];
    __shared__ float Bs[16][128];
    int tid = threadIdx.x;
    int tx = tid & 15, ty = tid >> 4;
    int row0 = blockIdx.y * 128, col0 = blockIdx.x * 128;
    float acc[8][8] = {};
    for (int k0 = 0; k0 < K; k0 += 16) {
        #pragma unroll
        for (int i = 0; i < 2; ++i) {
            int chunk = tid * 2 + i;
            int r = chunk >> 2, kq = (chunk & 3) << 2;
            float4 v = *(const float4*)(A + (size_t)(row0 + r) * K + k0 + kq);
            As[kq + 0][r] = v.x; As[kq + 1][r] = v.y;
            As[kq + 2][r] = v.z; As[kq + 3][r] = v.w;
        }
        #pragma unroll
        for (int i = 0; i < 2; ++i) {
            int chunk = tid * 2 + i;
            int kr = chunk >> 5, c4 = (chunk & 31) << 2;
            *(float4*)&Bs[kr][c4] = *(const float4*)(W + (size_t)(k0 + kr) * N + col0 + c4);
        }
        __syncthreads();
        #pragma unroll
        for (int kk = 0; kk < 16; ++kk) {
            float a[8], b[8];
            *(float4*)(a)     = *(float4*)&As[kk][ty * 8];
            *(float4*)(a + 4) = *(float4*)&As[kk][ty * 8 + 4];
            *(float4*)(b)     = *(float4*)&Bs[kk][tx * 8];
            *(float4*)(b + 4) = *(float4*)&Bs[kk][tx * 8 + 4];
            #pragma unroll
            for (int i = 0; i < 8; ++i)
                #pragma unroll
                for (int j = 0; j < 8; ++j)
                    acc[i][j] = fmaf(a[i], b[j], acc[i][j]);
        }
        __syncthreads();
    }
    #pragma unroll
    for (int i = 0; i < 8; ++i) {
        int row = row0 + ty * 8 + i;
        #pragma unroll
        for (int j4 = 0; j4 < 2; ++j4) {
            int col = col0 + tx * 8 + j4 * 4;
            float4 o;
            o.x = acc[i][j4*4+0]; o.y = acc[i][j4*4+1];
            o.z = acc[i][j4*4+2]; o.w = acc[i][j4*4+3];
            if (R) {
                float4 r = *(const float4*)(R + (size_t)row * N + col);
                o.x += r.x; o.y += r.y; o.z += r.z; o.w += r.w;
            }
            *(float4*)(C + (size_t)row * N + col) = o;
        }
    }
}

#define BM 64
#define BN 64
#define BK 16
__global__ void sgemm_nn(const float* __restrict__ A, const float* __restrict__ W,
                         const float* __restrict__ R, float* __restrict__ C,
                         int M, int N, int K) {
    __shared__ float As[BK][BM];
    __shared__ float Bs[BK][BN];
    int tid = threadIdx.x;
    int tx = tid & 15, ty = tid >> 4;
    int row0 = blockIdx.y * BM, col0 = blockIdx.x * BN;
    float acc[4][4] = {};
    for (int k0 = 0; k0 < K; k0 += BK) {
        {
            int r = tid >> 2, kq = (tid & 3) << 2;
            float4 v = *(const float4*)(A + (size_t)(row0 + r) * K + k0 + kq);
            As[kq + 0][r] = v.x; As[kq + 1][r] = v.y;
            As[kq + 2][r] = v.z; As[kq + 3][r] = v.w;
        }
        {
            int r = tid >> 4, c = (tid & 15) << 2;
            *(float4*)&Bs[r][c] = *(const float4*)(W + (size_t)(k0 + r) * N + col0 + c);
        }
        __syncthreads();
        #pragma unroll
        for (int kk = 0; kk < BK; ++kk) {
            float a[4], b[4];
            *(float4*)a = *(float4*)&As[kk][ty << 2];
            *(float4*)b = *(float4*)&Bs[kk][tx << 2];
            #pragma unroll
            for (int i = 0; i < 4; ++i)
                #pragma unroll
                for (int j = 0; j < 4; ++j)
                    acc[i][j] += a[i] * b[j];
        }
        __syncthreads();
    }
    #pragma unroll
    for (int i = 0; i < 4; ++i) {
        int row = row0 + (ty << 2) + i;
        float4 o;
        o.x = acc[i][0]; o.y = acc[i][1]; o.z = acc[i][2]; o.w = acc[i][3];
        if (R) {
            float4 r = *(const float4*)(R + (size_t)row * N + col0 + (tx << 2));
            o.x += r.x; o.y += r.y; o.z += r.z; o.w += r.w;
        }
        *(float4*)(C + (size_t)row * N + col0 + (tx << 2)) = o;
    }
}

__global__ void sgemm_nt_w(const float* __restrict__ A, const float* __restrict__ Bm,
                           float* __restrict__ C) {
    __shared__ float As[BK][BM];
    __shared__ float Bs[BK][BN];
    int tid = threadIdx.x;
    int tx = tid & 15, ty = tid >> 4;
    int row0 = blockIdx.y * BM, col0 = blockIdx.x * BN;
    float acc[4][4] = {};
    for (int k0 = 0; k0 < C_; k0 += BK) {
        int r = tid >> 2, kq = (tid & 3) << 2;
        {
            float4 v = *(const float4*)(A + (size_t)(row0 + r) * C_ + k0 + kq);
            As[kq + 0][r] = v.x; As[kq + 1][r] = v.y;
            As[kq + 2][r] = v.z; As[kq + 3][r] = v.w;
        }
        {
            float4 v = *(const float4*)(Bm + (size_t)(col0 + r) * C_ + k0 + kq);
            Bs[kq + 0][r] = v.x; Bs[kq + 1][r] = v.y;
            Bs[kq + 2][r] = v.z; Bs[kq + 3][r] = v.w;
        }
        __syncthreads();
        #pragma unroll
        for (int kk = 0; kk < BK; ++kk) {
            float a[4], b[4];
            *(float4*)a = *(float4*)&As[kk][ty << 2];
            *(float4*)b = *(float4*)&Bs[kk][tx << 2];
            #pragma unroll
            for (int i = 0; i < 4; ++i)
                #pragma unroll
                for (int j = 0; j < 4; ++j)
                    acc[i][j] += a[i] * b[j];
        }
        __syncthreads();
    }
    #pragma unroll
    for (int i = 0; i < 4; ++i) {
        int row = row0 + (ty << 2) + i;
        float4 o;
        o.x = acc[i][0]; o.y = acc[i][1]; o.z = acc[i][2]; o.w = acc[i][3];
        *(float4*)(C + (size_t)row * C_ + col0 + (tx << 2)) = o;
    }
}

// ---------------- attention (validated) ----------------
__global__ void attn_kernel(const float* __restrict__ q, const float* __restrict__ ref,
                            const int* __restrict__ idx, float* __restrict__ ctx) {
    int row = blockIdx.x, b = row >> 10;
    int tid = threadIdx.x, warp = tid >> 5, lane = tid & 31;
    __shared__ float s_logits[KNN];
    __shared__ int   s_idx[KNN];
    if (tid < KNN) s_idx[tid] = idx[(size_t)row * KNN + tid];
    __syncthreads();
    const float* qrow = q + (size_t)row * C_;
    const float scale = 0.04419417382415922f;   // 1/sqrt(512)
    #pragma unroll
    for (int j = 0; j < 4; ++j) {
        int kk = warp * 4 + j;
        const float* krow = ref + ((size_t)b * M_ + s_idx[kk]) * C_;
        float acc = 0.f;
        #pragma unroll
        for (int c = lane * 4; c < C_; c += 128) {
            float4 qa = *(const float4*)(qrow + c);
            float4 ka = *(const float4*)(krow + c);
            acc += qa.x * ka.x + qa.y * ka.y + qa.z * ka.z + qa.w * ka.w;
        }
        #pragma unroll
        for (int o = 16; o; o >>= 1) acc += __shfl_down_sync(0xFFFFFFFFu, acc, o);
        if (lane == 0) s_logits[kk] = acc * scale;
    }
    __syncthreads();
    float mx = -INFINITY;
    #pragma unroll
    for (int k = 0; k < KNN; ++k) mx = fmaxf(mx, s_logits[k]);
    float wv[KNN]; float wsum = 0.f;
    #pragma unroll
    for (int k = 0; k < KNN; ++k) { wv[k] = expf(s_logits[k] - mx); wsum += wv[k]; }
    float inv = 1.0f / wsum;
    int c = tid * 4;
    float4 acc4 = {0.f, 0.f, 0.f, 0.f};
    #pragma unroll
    for (int k = 0; k < KNN; ++k) {
        const float4 va = *(const float4*)(ref + ((size_t)b * M_ + s_idx[k]) * C_ + c);
        float wk = wv[k] * inv;
        acc4.x += wk * va.x; acc4.y += wk * va.y;
        acc4.z += wk * va.z; acc4.w += wk * va.w;
    }
    *(float4*)(ctx + (size_t)row * C_ + c) = acc4;
}

// ---------------- launch: fork q-GEMM onto a side stream under the selection chain -----
static cudaStream_t s_side = nullptr;
static cudaEvent_t  s_evFork = nullptr, s_evJoin = nullptr;

extern "C" void kernel_launch(void* const* d_in, const int* in_sizes, int n_in,
                              void* d_out, int out_size) {
    if (!s_side) {   // one-time infra creation (first call is the uncaptured correctness run)
        cudaStreamCreateWithFlags(&s_side, cudaStreamNonBlocking);
        cudaEventCreateWithFlags(&s_evFork, cudaEventDisableTiming);
        cudaEventCreateWithFlags(&s_evJoin, cudaEventDisableTiming);
    }
    const float* slots_in = (const float*)d_in[0];
    const float* ref_list = (const float*)d_in[1];
    const float* Wq = (const float*)d_in[2];
    const float* Wk = (const float*)d_in[3];
    const float* Wv = (const float*)d_in[4];
    const float* Wo = (const float*)d_in[5];
    const float* ref = ref_list + ((size_t)in_sizes[1] - (size_t)B_ * M_ * C_);
    float* out = (float*)d_out;

    float *p_nr, *p_nt, *p_q, *p_ctx, *p_slots, *p_G, *p_Wvo;
    bf16 *p_corr, *p_nr_bf, *p_nt_bf;
    int *p_cand, *p_idx;
    cudaGetSymbolAddress((void**)&p_nr, g_nr);       cudaGetSymbolAddress((void**)&p_nt, g_nt);
    cudaGetSymbolAddress((void**)&p_corr, g_corr);   cudaGetSymbolAddress((void**)&p_q, g_q);
    cudaGetSymbolAddress((void**)&p_ctx, g_ctx);     cudaGetSymbolAddress((void**)&p_slots, g_slots);
    cudaGetSymbolAddress((void**)&p_G, g_G);         cudaGetSymbolAddress((void**)&p_Wvo, g_Wvo);
    cudaGetSymbolAddress((void**)&p_nr_bf, g_nr_bf); cudaGetSymbolAddress((void**)&p_nt_bf, g_nt_bf);
    cudaGetSymbolAddress((void**)&p_cand, g_cand);   cudaGetSymbolAddress((void**)&p_idx, g_idx);

    // ---- precompute ----
    normalize_rows_bf<<<B_ * M_, 128>>>(ref, p_nr, p_nr_bf);
    dim3 gW(C_ / BN, C_ / BM);
    sgemm_nt_w<<<gW, 256>>>(Wq, Wk, p_G);                        // G = Wq @ Wk^T
    sgemm_nn<<<gW, 256>>>(Wv, Wo, nullptr, p_Wvo, C_, C_, C_);   // Wvo = Wv @ Wo

    const float* cur = slots_in;
    for (int it = 0; it < ITERS; ++it) {
        float* dst = (it == ITERS - 1) ? out : p_slots;

        // fork: q' = cur @ G depends only on cur (and G) — run on side stream
        cudaEventRecord(s_evFork, 0);
        cudaStreamWaitEvent(s_side, s_evFork, 0);
        dim3 gQ(C_ / 128, (B_ * N_) / 128);
        sgemm_nn_128<<<gQ, 256, 0, s_side>>>(cur, p_G, nullptr, p_q, B_ * N_, C_, C_);
        cudaEventRecord(s_evJoin, s_side);

        // selection chain on main stream
        normalize_rows_bf<<<B_ * N_, 128>>>(cur, p_nt, p_nt_bf);
        dim3 gCorr(M_ / 128, N_ / 128, B_);
        gemm_corr<<<gCorr, 256>>>(p_nt_bf, p_nr_bf, p_corr);
        cand_kernel<<<(B_ * N_) / 8, 256>>>(p_corr, p_cand);
        rescore_kernel<<<(B_ * N_) / 8, 256>>>(p_nt, p_nr, p_cand, p_idx);

        // join before attn (needs q + idx)
        cudaStreamWaitEvent(0, s_evJoin, 0);
        attn_kernel<<<B_ * N_, 128>>>(p_q, ref, p_idx, p_ctx);

        sgemm_nn_128<<<gQ, 256>>>(p_ctx, p_Wvo, cur, dst, B_ * N_, C_, C_);

        cur = p_slots;
    }
}